// round 1
// baseline (speedup 1.0000x reference)
#include <cuda_runtime.h>
#include <cstdint>

#define S_LEN 2048
#define HID   4096
#define NH    32
#define HD    128
#define ROPE  64
#define QR    1536
#define KVR   896
#define QDIM  192                 // ROPE + HD
#define EPS   1e-6f
#define SCALE_F 0.07216878364870322f  // 1/sqrt(192)

// ---------------- scratch (device globals; no allocation allowed) ----------------
__device__ float g_qlat[S_LEN * QR];              // 12.6 MB
__device__ float g_q[S_LEN * NH * QDIM];          // 50 MB
__device__ float g_kv[S_LEN * (KVR + ROPE)];      // 7.9 MB
__device__ float g_kvn[S_LEN * KVR];              // 7.3 MB
__device__ float g_kvup[S_LEN * NH * 2 * HD];     // 67 MB
__device__ float g_qT[NH * QDIM * S_LEN];         // 50 MB  [h][d][s], pre-scaled
__device__ float g_kT[NH * QDIM * S_LEN];         // 50 MB  [h][d][s]
__device__ float g_attn[S_LEN * NH * HD];         // 33.5 MB [s][h*128+d]

// ---------------- SGEMM: C[M,N] = A[M,K] * B[N,K]^T (all row-major) ----------------
// 128x128 tile, BK=8, 256 threads, 8x8 micro-tile per thread.
__global__ void __launch_bounds__(256) sgemm_nt(const float* __restrict__ A,
                                                const float* __restrict__ B,
                                                float* __restrict__ C,
                                                int M, int N, int K) {
    __shared__ float sA[8][128];
    __shared__ float sB[8][128];

    const int bm = blockIdx.y * 128;
    const int bn = blockIdx.x * 128;
    const int tid = threadIdx.x;
    const int tx = tid & 15;   // n direction
    const int ty = tid >> 4;   // m direction

    // load mapping: each thread one float4 from A and one from B
    const int lr = tid >> 1;          // 0..127 row within tile
    const int lk = (tid & 1) * 4;     // 0 or 4

    const float* Aptr = A + (size_t)(bm + lr) * K + lk;
    const bool bvalid = (bn + lr) < N;
    const float* Bptr = B + (size_t)(bvalid ? (bn + lr) : 0) * K + lk;

    float acc[8][8];
#pragma unroll
    for (int i = 0; i < 8; i++)
#pragma unroll
        for (int j = 0; j < 8; j++) acc[i][j] = 0.f;

    float4 a = *(const float4*)(Aptr);
    float4 b = bvalid ? *(const float4*)(Bptr) : make_float4(0.f, 0.f, 0.f, 0.f);

    for (int k0 = 0; k0 < K; k0 += 8) {
        sA[lk + 0][lr] = a.x; sA[lk + 1][lr] = a.y; sA[lk + 2][lr] = a.z; sA[lk + 3][lr] = a.w;
        sB[lk + 0][lr] = b.x; sB[lk + 1][lr] = b.y; sB[lk + 2][lr] = b.z; sB[lk + 3][lr] = b.w;
        __syncthreads();

        if (k0 + 8 < K) {
            a = *(const float4*)(Aptr + k0 + 8);
            b = bvalid ? *(const float4*)(Bptr + k0 + 8) : make_float4(0.f, 0.f, 0.f, 0.f);
        }

#pragma unroll
        for (int k = 0; k < 8; ++k) {
            float4 a0 = *(const float4*)&sA[k][ty * 8];
            float4 a1 = *(const float4*)&sA[k][ty * 8 + 4];
            float4 b0 = *(const float4*)&sB[k][tx * 8];
            float4 b1 = *(const float4*)&sB[k][tx * 8 + 4];
            float av[8] = {a0.x, a0.y, a0.z, a0.w, a1.x, a1.y, a1.z, a1.w};
            float bv[8] = {b0.x, b0.y, b0.z, b0.w, b1.x, b1.y, b1.z, b1.w};
#pragma unroll
            for (int i = 0; i < 8; i++)
#pragma unroll
                for (int j = 0; j < 8; j++)
                    acc[i][j] = fmaf(av[i], bv[j], acc[i][j]);
        }
        __syncthreads();
    }

#pragma unroll
    for (int i = 0; i < 8; i++) {
        const int row = bm + ty * 8 + i;   // M always multiple of 128 here
#pragma unroll
        for (int j = 0; j < 8; j++) {
            const int col = bn + tx * 8 + j;
            if (col < N) C[(size_t)row * N + col] = acc[i][j];
        }
    }
}

// ---------------- RMSNorm (block per row) ----------------
__global__ void rmsnorm_kernel(const float* __restrict__ in, const float* __restrict__ w,
                               float* __restrict__ out, int n, int in_stride, int out_stride) {
    const int row = blockIdx.x;
    const float* p = in + (size_t)row * in_stride;
    float ss = 0.f;
    for (int i = threadIdx.x; i < n; i += blockDim.x) {
        float v = p[i];
        ss += v * v;
    }
    __shared__ float red[8];
#pragma unroll
    for (int o = 16; o > 0; o >>= 1) ss += __shfl_xor_sync(0xffffffff, ss, o);
    if ((threadIdx.x & 31) == 0) red[threadIdx.x >> 5] = ss;
    __syncthreads();
    if (threadIdx.x < 8) {
        float v = red[threadIdx.x];
#pragma unroll
        for (int o = 4; o > 0; o >>= 1) v += __shfl_xor_sync(0xff, v, o);
        if (threadIdx.x == 0) red[0] = v;
    }
    __syncthreads();
    const float scale = rsqrtf(red[0] / (float)n + EPS);
    float* q = out + (size_t)row * out_stride;
    for (int i = threadIdx.x; i < n; i += blockDim.x) q[i] = p[i] * scale * w[i];
}

// ---------------- RoPE + transpose-pack into [h][d][s] layout ----------------
__global__ void rope_pack(const float* __restrict__ q, const float* __restrict__ kv,
                          const float* __restrict__ kvup,
                          const float* __restrict__ cosT, const float* __restrict__ sinT,
                          float* __restrict__ qT, float* __restrict__ kT) {
    const int s = blockIdx.x;
    const int h = blockIdx.y;
    const int d = threadIdx.x;  // 0..191

    float qv, kvv;
    if (d < ROPE) {
        const float c = cosT[s * ROPE + d];
        const float sn = sinT[s * ROPE + d];
        const int dro = (d < 32) ? d + 32 : d - 32;
        const float sgn = (d < 32) ? -1.f : 1.f;
        const float xq = q[(size_t)s * (NH * QDIM) + h * QDIM + d];
        const float xqo = q[(size_t)s * (NH * QDIM) + h * QDIM + dro];
        qv = xq * c + sgn * xqo * sn;
        const float xk = kv[(size_t)s * (KVR + ROPE) + KVR + d];
        const float xko = kv[(size_t)s * (KVR + ROPE) + KVR + dro];
        kvv = xk * c + sgn * xko * sn;
    } else {
        qv = q[(size_t)s * (NH * QDIM) + h * QDIM + d];
        kvv = kvup[(size_t)s * (NH * 2 * HD) + h * (2 * HD) + (d - ROPE)];
    }
    qT[((size_t)h * QDIM + d) * S_LEN + s] = qv * SCALE_F;  // fold softmax scale into Q
    kT[((size_t)h * QDIM + d) * S_LEN + s] = kvv;
}

// ---------------- Flash attention (causal) ----------------
// Block: one head, 64 queries. Tiles of 64 keys. 256 threads = 16x16 (ty, tx).
// Scores: 4x4 per thread.  O: 4 rows x 8 dv-cols per thread.
#define AM 64
#define AN 64
#define SP_STRIDE 68
#define ATTN_SMEM ((QDIM * AM * 2 + AN * HD + AN * SP_STRIDE) * 4)

__global__ void __launch_bounds__(256) attn_kernel(const float* __restrict__ qT,
                                                   const float* __restrict__ kT,
                                                   const float* __restrict__ kvup,
                                                   float* __restrict__ outp) {
    extern __shared__ float sh[];
    float* sQ = sh;                       // [192][64]  (d-major)
    float* sK = sQ + QDIM * AM;           // [192][64]
    float* sV = sK + QDIM * AN;           // [64][128]
    float* sP = sV + AN * HD;             // [64][68]   Pt[j][i]

    // heavy blocks (large qb) first for better tail behavior
    const int qb = (gridDim.x - 1 - blockIdx.x) * AM;
    const int h = blockIdx.y;
    const int tid = threadIdx.x;
    const int tx = tid & 15;
    const int ty = tid >> 4;

    const float* qbase = qT + (size_t)h * QDIM * S_LEN;
    const float* kbase = kT + (size_t)h * QDIM * S_LEN;
    const float* vbase = kvup + h * (2 * HD) + HD;

    // load Q tile (coalesced, conflict-free)
    for (int p = tid; p < QDIM * AM; p += 256) {
        const int d = p >> 6, j = p & 63;
        sQ[d * AM + j] = qbase[(size_t)d * S_LEN + qb + j];
    }

    float m_r[4], l_r[4], o_r[4][8];
#pragma unroll
    for (int a = 0; a < 4; a++) {
        m_r[a] = -1e30f;
        l_r[a] = 0.f;
#pragma unroll
        for (int c = 0; c < 8; c++) o_r[a][c] = 0.f;
    }

    const int ntiles = qb / AN + 1;
    for (int t = 0; t < ntiles; ++t) {
        const int kb = t * AN;
        __syncthreads();  // protect sK/sV/sP from previous iteration readers
        for (int p = tid; p < QDIM * AN; p += 256) {
            const int d = p >> 6, j = p & 63;
            sK[d * AN + j] = kbase[(size_t)d * S_LEN + kb + j];
        }
        for (int p = tid; p < AN * HD; p += 256) {
            const int j = p >> 7, dv = p & 127;
            sV[j * HD + dv] = vbase[(size_t)(kb + j) * (NH * 2 * HD) + dv];
        }
        __syncthreads();

        // scores: s[a][b] = sum_d Q[d][i0+a]*K[d][j0+b]
        float s[4][4];
#pragma unroll
        for (int a = 0; a < 4; a++)
#pragma unroll
            for (int b = 0; b < 4; b++) s[a][b] = 0.f;

#pragma unroll 4
        for (int k = 0; k < QDIM; ++k) {
            float4 qa = *(const float4*)&sQ[k * AM + ty * 4];
            float4 kb4 = *(const float4*)&sK[k * AN + tx * 4];
            float av[4] = {qa.x, qa.y, qa.z, qa.w};
            float bv[4] = {kb4.x, kb4.y, kb4.z, kb4.w};
#pragma unroll
            for (int a = 0; a < 4; a++)
#pragma unroll
                for (int b = 0; b < 4; b++)
                    s[a][b] = fmaf(av[a], bv[b], s[a][b]);
        }

        // causal mask on diagonal tile (kb == qb)
        if (t == ntiles - 1) {
#pragma unroll
            for (int a = 0; a < 4; a++)
#pragma unroll
                for (int b = 0; b < 4; b++)
                    if (tx * 4 + b > ty * 4 + a) s[a][b] = -1e30f;
        }

        // online softmax per row (rows shared by the 16 tx lanes)
#pragma unroll
        for (int a = 0; a < 4; a++) {
            float mx = fmaxf(fmaxf(s[a][0], s[a][1]), fmaxf(s[a][2], s[a][3]));
#pragma unroll
            for (int o = 1; o < 16; o <<= 1) mx = fmaxf(mx, __shfl_xor_sync(0xffffffff, mx, o));
            const float mnew = fmaxf(m_r[a], mx);
            const float alpha = __expf(m_r[a] - mnew);
            float rs = 0.f;
#pragma unroll
            for (int b = 0; b < 4; b++) {
                const float pv = __expf(s[a][b] - mnew);
                s[a][b] = pv;
                rs += pv;
            }
#pragma unroll
            for (int o = 1; o < 16; o <<= 1) rs += __shfl_xor_sync(0xffffffff, rs, o);
            l_r[a] = l_r[a] * alpha + rs;
            m_r[a] = mnew;
#pragma unroll
            for (int c = 0; c < 8; c++) o_r[a][c] *= alpha;
            // write P transposed: sP[j][i]
#pragma unroll
            for (int b = 0; b < 4; b++)
                sP[(tx * 4 + b) * SP_STRIDE + ty * 4 + a] = s[a][b];
        }
        __syncthreads();

        // O += P * V : rows i0=ty*4 (float4 from Pt), cols dv0=tx*8
#pragma unroll 4
        for (int j = 0; j < AN; ++j) {
            float4 pv = *(const float4*)&sP[j * SP_STRIDE + ty * 4];
            float4 v0 = *(const float4*)&sV[j * HD + tx * 8];
            float4 v1 = *(const float4*)&sV[j * HD + tx * 8 + 4];
            float pa[4] = {pv.x, pv.y, pv.z, pv.w};
            float vv[8] = {v0.x, v0.y, v0.z, v0.w, v1.x, v1.y, v1.z, v1.w};
#pragma unroll
            for (int a = 0; a < 4; a++)
#pragma unroll
                for (int c = 0; c < 8; c++)
                    o_r[a][c] = fmaf(pa[a], vv[c], o_r[a][c]);
        }
    }

    // final normalize + store: outp[s][h*128 + dv]
#pragma unroll
    for (int a = 0; a < 4; a++) {
        const float inv = 1.f / l_r[a];
        const int row = qb + ty * 4 + a;
        float* dst = outp + (size_t)row * (NH * HD) + h * HD + tx * 8;
#pragma unroll
        for (int c = 0; c < 8; c++) dst[c] = o_r[a][c] * inv;
    }
}

// ---------------- launch ----------------
extern "C" void kernel_launch(void* const* d_in, const int* in_sizes, int n_in,
                              void* d_out, int out_size) {
    const float* x          = (const float*)d_in[0];
    const float* cosp       = (const float*)d_in[1];
    const float* sinp       = (const float*)d_in[2];
    const float* q_a_w      = (const float*)d_in[3];
    const float* q_a_norm_w = (const float*)d_in[4];
    const float* q_b_w      = (const float*)d_in[5];
    const float* kv_a_w     = (const float*)d_in[6];
    const float* kv_a_norm_w= (const float*)d_in[7];
    const float* kv_b_w     = (const float*)d_in[8];
    const float* o_w        = (const float*)d_in[9];

    float *qlat, *q, *kv, *kvn, *kvup, *qT, *kT, *attn;
    cudaGetSymbolAddress((void**)&qlat, g_qlat);
    cudaGetSymbolAddress((void**)&q,    g_q);
    cudaGetSymbolAddress((void**)&kv,   g_kv);
    cudaGetSymbolAddress((void**)&kvn,  g_kvn);
    cudaGetSymbolAddress((void**)&kvup, g_kvup);
    cudaGetSymbolAddress((void**)&qT,   g_qT);
    cudaGetSymbolAddress((void**)&kT,   g_kT);
    cudaGetSymbolAddress((void**)&attn, g_attn);

    // 1) q_lat_raw = x @ q_a_w^T   [2048,1536]
    sgemm_nt<<<dim3(QR / 128, S_LEN / 128), 256>>>(x, q_a_w, qlat, S_LEN, QR, HID);
    // 2) rmsnorm(q_lat)
    rmsnorm_kernel<<<S_LEN, 256>>>(qlat, q_a_norm_w, qlat, QR, QR, QR);
    // 3) q = q_lat @ q_b_w^T       [2048,6144]
    sgemm_nt<<<dim3((NH * QDIM) / 128, S_LEN / 128), 256>>>(qlat, q_b_w, q, S_LEN, NH * QDIM, QR);
    // 4) kv = x @ kv_a_w^T         [2048,960]
    sgemm_nt<<<dim3((KVR + ROPE + 127) / 128, S_LEN / 128), 256>>>(x, kv_a_w, kv, S_LEN, KVR + ROPE, HID);
    // 5) rmsnorm(kv[:, :896]) -> kvn
    rmsnorm_kernel<<<S_LEN, 256>>>(kv, kv_a_norm_w, kvn, KVR, KVR + ROPE, KVR);
    // 6) kv_up = kvn @ kv_b_w^T    [2048,8192]
    sgemm_nt<<<dim3((NH * 2 * HD) / 128, S_LEN / 128), 256>>>(kvn, kv_b_w, kvup, S_LEN, NH * 2 * HD, KVR);
    // 7) rope + pack (transposed, scale folded into Q)
    rope_pack<<<dim3(S_LEN, NH), QDIM>>>(q, kv, kvup, cosp, sinp, qT, kT);
    // 8) causal flash attention
    cudaFuncSetAttribute(attn_kernel, cudaFuncAttributeMaxDynamicSharedMemorySize, ATTN_SMEM);
    attn_kernel<<<dim3(S_LEN / AM, NH), 256, ATTN_SMEM>>>(qT, kT, kvup, attn);
    // 9) out = attn @ o_w^T        [2048,4096]
    sgemm_nt<<<dim3(HID / 128, S_LEN / 128), 256>>>(attn, o_w, (float*)d_out, S_LEN, HID, HID);
}

// round 3
// speedup vs baseline: 1.6074x; 1.6074x over previous
#include <cuda_runtime.h>
#include <cuda_bf16.h>
#include <cstdint>

#define S_LEN 2048
#define HID   4096
#define NH    32
#define HD    128
#define ROPE  64
#define QR    1536
#define KVR   896
#define QDIM  192                 // ROPE + HD
#define EPS   1e-6f
#define SCALE_F 0.07216878364870322f  // 1/sqrt(192)

// ---------------- scratch (device globals; no allocation allowed) ----------------
__device__ float g_qlat[S_LEN * QR];
__device__ float g_q[S_LEN * NH * QDIM];
__device__ float g_kv[S_LEN * (KVR + ROPE)];
__device__ float g_kvn[S_LEN * KVR];
__device__ float g_kvup[S_LEN * NH * 2 * HD];
__device__ float g_qT[NH * QDIM * S_LEN];
__device__ float g_kT[NH * QDIM * S_LEN];
__device__ float g_attn[S_LEN * NH * HD];

// bf16 hi/lo split buffers
__device__ __nv_bfloat16 g_xh[S_LEN * HID];
__device__ __nv_bfloat16 g_xl[S_LEN * HID];
__device__ __nv_bfloat16 g_ah[S_LEN * HID];   // activation scratch (max 2048x4096)
__device__ __nv_bfloat16 g_al[S_LEN * HID];
__device__ __nv_bfloat16 g_wh[HID * HID];     // weight scratch (max 4096x4096)
__device__ __nv_bfloat16 g_wl[HID * HID];

// ---------------- fp32 -> (bf16 hi, bf16 lo) split ----------------
__global__ void split_kernel(const float* __restrict__ in, __nv_bfloat16* __restrict__ hi,
                             __nv_bfloat16* __restrict__ lo, int n) {
    int i = (blockIdx.x * blockDim.x + threadIdx.x) * 4;
    if (i >= n) return;
    float4 v = *(const float4*)(in + i);
    float vv[4] = {v.x, v.y, v.z, v.w};
    __nv_bfloat16 h[4], l[4];
#pragma unroll
    for (int j = 0; j < 4; j++) {
        h[j] = __float2bfloat16(vv[j]);
        l[j] = __float2bfloat16(vv[j] - __bfloat162float(h[j]));
    }
    __nv_bfloat162* hp = (__nv_bfloat162*)(hi + i);
    __nv_bfloat162* lp = (__nv_bfloat162*)(lo + i);
    hp[0] = __halves2bfloat162(h[0], h[1]);
    hp[1] = __halves2bfloat162(h[2], h[3]);
    lp[0] = __halves2bfloat162(l[0], l[1]);
    lp[1] = __halves2bfloat162(l[2], l[3]);
}

// ---------------- split-bf16 tensor-core GEMM: C[M,N] = A[M,K] @ B[N,K]^T ----------------
// 128x128x32 tile, 256 threads (8 warps in 2x4), warp tile 64x32, mma.m16n8k16.
#define BM 128
#define BN 128
#define BK 32
#define LDSB 40   // smem row stride in bf16 elems (padding kills ldmatrix conflicts)

#define MMA_BF16(c, a, b)                                                            \
    asm volatile(                                                                    \
        "mma.sync.aligned.m16n8k16.row.col.f32.bf16.bf16.f32 "                       \
        "{%0,%1,%2,%3}, {%4,%5,%6,%7}, {%8,%9}, {%0,%1,%2,%3};"                      \
        : "+f"(c[0]), "+f"(c[1]), "+f"(c[2]), "+f"(c[3])                             \
        : "r"(a[0]), "r"(a[1]), "r"(a[2]), "r"(a[3]), "r"(b[0]), "r"(b[1]))

__global__ void __launch_bounds__(256) gemm_bf16x3(
    const __nv_bfloat16* __restrict__ Ah, const __nv_bfloat16* __restrict__ Al,
    const __nv_bfloat16* __restrict__ Bh, const __nv_bfloat16* __restrict__ Bl,
    float* __restrict__ C, int M, int N, int K) {
    __shared__ __nv_bfloat16 sAh[BM * LDSB];
    __shared__ __nv_bfloat16 sAl[BM * LDSB];
    __shared__ __nv_bfloat16 sBh[BN * LDSB];
    __shared__ __nv_bfloat16 sBl[BN * LDSB];

    const int bm = blockIdx.y * BM;
    const int bn = blockIdx.x * BN;
    const int tid = threadIdx.x;
    const int wid = tid >> 5, lane = tid & 31;
    const int wm = (wid >> 2) * 64;   // warp m offset in tile
    const int wn = (wid & 3) * 32;    // warp n offset in tile

    // gmem load mapping: thread t -> row lr (0..127), k-segment lk (0 or 16)
    const int lr = tid >> 1;
    const int lk = (tid & 1) * 16;
    const __nv_bfloat16* gAh = Ah + (size_t)(bm + lr) * K + lk;
    const __nv_bfloat16* gAl = Al + (size_t)(bm + lr) * K + lk;
    const int brow = min(bn + lr, N - 1);   // clamp for N not multiple of 128
    const __nv_bfloat16* gBh = Bh + (size_t)brow * K + lk;
    const __nv_bfloat16* gBl = Bl + (size_t)brow * K + lk;

    float acc[4][4][4];
#pragma unroll
    for (int i = 0; i < 4; i++)
#pragma unroll
        for (int j = 0; j < 4; j++)
#pragma unroll
            for (int r = 0; r < 4; r++) acc[i][j][r] = 0.f;

    // register prefetch of first tile
    uint4 pah0 = *(const uint4*)(gAh),     pah1 = *(const uint4*)(gAh + 8);
    uint4 pal0 = *(const uint4*)(gAl),     pal1 = *(const uint4*)(gAl + 8);
    uint4 pbh0 = *(const uint4*)(gBh),     pbh1 = *(const uint4*)(gBh + 8);
    uint4 pbl0 = *(const uint4*)(gBl),     pbl1 = *(const uint4*)(gBl + 8);

    for (int k0 = 0; k0 < K; k0 += BK) {
        __syncthreads();
        *(uint4*)&sAh[lr * LDSB + lk] = pah0;  *(uint4*)&sAh[lr * LDSB + lk + 8] = pah1;
        *(uint4*)&sAl[lr * LDSB + lk] = pal0;  *(uint4*)&sAl[lr * LDSB + lk + 8] = pal1;
        *(uint4*)&sBh[lr * LDSB + lk] = pbh0;  *(uint4*)&sBh[lr * LDSB + lk + 8] = pbh1;
        *(uint4*)&sBl[lr * LDSB + lk] = pbl0;  *(uint4*)&sBl[lr * LDSB + lk + 8] = pbl1;
        __syncthreads();

        if (k0 + BK < K) {
            pah0 = *(const uint4*)(gAh + k0 + BK);  pah1 = *(const uint4*)(gAh + k0 + BK + 8);
            pal0 = *(const uint4*)(gAl + k0 + BK);  pal1 = *(const uint4*)(gAl + k0 + BK + 8);
            pbh0 = *(const uint4*)(gBh + k0 + BK);  pbh1 = *(const uint4*)(gBh + k0 + BK + 8);
            pbl0 = *(const uint4*)(gBl + k0 + BK);  pbl1 = *(const uint4*)(gBl + k0 + BK + 8);
        }

#pragma unroll
        for (int kk = 0; kk < BK; kk += 16) {
            uint32_t a_h[4][4], a_l[4][4], b_h[4][2], b_l[4][2];
            const int ar = wm + (lane & 15);
            const int ac = kk + (lane >> 4) * 8;
#pragma unroll
            for (int mi = 0; mi < 4; mi++) {
                uint32_t adh = (uint32_t)__cvta_generic_to_shared(&sAh[(ar + mi * 16) * LDSB + ac]);
                asm volatile("ldmatrix.sync.aligned.m8n8.x4.shared.b16 {%0,%1,%2,%3}, [%4];"
                             : "=r"(a_h[mi][0]), "=r"(a_h[mi][1]), "=r"(a_h[mi][2]), "=r"(a_h[mi][3])
                             : "r"(adh));
                uint32_t adl = (uint32_t)__cvta_generic_to_shared(&sAl[(ar + mi * 16) * LDSB + ac]);
                asm volatile("ldmatrix.sync.aligned.m8n8.x4.shared.b16 {%0,%1,%2,%3}, [%4];"
                             : "=r"(a_l[mi][0]), "=r"(a_l[mi][1]), "=r"(a_l[mi][2]), "=r"(a_l[mi][3])
                             : "r"(adl));
            }
            // B stored [n][k] (k contiguous) == K x N col-major -> NON-trans ldmatrix
            const int br = wn + (lane & 7);
            const int bc = kk + ((lane >> 3) & 1) * 8;
#pragma unroll
            for (int nj = 0; nj < 4; nj++) {
                uint32_t bdh = (uint32_t)__cvta_generic_to_shared(&sBh[(br + nj * 8) * LDSB + bc]);
                asm volatile("ldmatrix.sync.aligned.m8n8.x2.shared.b16 {%0,%1}, [%2];"
                             : "=r"(b_h[nj][0]), "=r"(b_h[nj][1]) : "r"(bdh));
                uint32_t bdl = (uint32_t)__cvta_generic_to_shared(&sBl[(br + nj * 8) * LDSB + bc]);
                asm volatile("ldmatrix.sync.aligned.m8n8.x2.shared.b16 {%0,%1}, [%2];"
                             : "=r"(b_l[nj][0]), "=r"(b_l[nj][1]) : "r"(bdl));
            }
#pragma unroll
            for (int mi = 0; mi < 4; mi++)
#pragma unroll
                for (int nj = 0; nj < 4; nj++) {
                    MMA_BF16(acc[mi][nj], a_h[mi], b_h[nj]);
                    MMA_BF16(acc[mi][nj], a_h[mi], b_l[nj]);
                    MMA_BF16(acc[mi][nj], a_l[mi], b_h[nj]);
                }
        }
    }

    // epilogue
#pragma unroll
    for (int mi = 0; mi < 4; mi++) {
#pragma unroll
        for (int nj = 0; nj < 4; nj++) {
            const int row0 = bm + wm + mi * 16 + (lane >> 2);
            const int col = bn + wn + nj * 8 + (lane & 3) * 2;
            if (col < N) {
                C[(size_t)row0 * N + col]       = acc[mi][nj][0];
                C[(size_t)row0 * N + col + 1]   = acc[mi][nj][1];
                C[(size_t)(row0 + 8) * N + col]     = acc[mi][nj][2];
                C[(size_t)(row0 + 8) * N + col + 1] = acc[mi][nj][3];
            }
        }
    }
}

// ---------------- RMSNorm (block per row) ----------------
__global__ void rmsnorm_kernel(const float* __restrict__ in, const float* __restrict__ w,
                               float* __restrict__ out, int n, int in_stride, int out_stride) {
    const int row = blockIdx.x;
    const float* p = in + (size_t)row * in_stride;
    float ss = 0.f;
    for (int i = threadIdx.x; i < n; i += blockDim.x) {
        float v = p[i];
        ss += v * v;
    }
    __shared__ float red[8];
#pragma unroll
    for (int o = 16; o > 0; o >>= 1) ss += __shfl_xor_sync(0xffffffff, ss, o);
    if ((threadIdx.x & 31) == 0) red[threadIdx.x >> 5] = ss;
    __syncthreads();
    if (threadIdx.x < 8) {
        float v = red[threadIdx.x];
#pragma unroll
        for (int o = 4; o > 0; o >>= 1) v += __shfl_xor_sync(0xff, v, o);
        if (threadIdx.x == 0) red[0] = v;
    }
    __syncthreads();
    const float scale = rsqrtf(red[0] / (float)n + EPS);
    float* q = out + (size_t)row * out_stride;
    for (int i = threadIdx.x; i < n; i += blockDim.x) q[i] = p[i] * scale * w[i];
}

// ---------------- RoPE + transpose-pack into [h][d][s] layout ----------------
__global__ void rope_pack(const float* __restrict__ q, const float* __restrict__ kv,
                          const float* __restrict__ kvup,
                          const float* __restrict__ cosT, const float* __restrict__ sinT,
                          float* __restrict__ qT, float* __restrict__ kT) {
    const int s = blockIdx.x;
    const int h = blockIdx.y;
    const int d = threadIdx.x;  // 0..191

    float qv, kvv;
    if (d < ROPE) {
        const float c = cosT[s * ROPE + d];
        const float sn = sinT[s * ROPE + d];
        const int dro = (d < 32) ? d + 32 : d - 32;
        const float sgn = (d < 32) ? -1.f : 1.f;
        const float xq = q[(size_t)s * (NH * QDIM) + h * QDIM + d];
        const float xqo = q[(size_t)s * (NH * QDIM) + h * QDIM + dro];
        qv = xq * c + sgn * xqo * sn;
        const float xk = kv[(size_t)s * (KVR + ROPE) + KVR + d];
        const float xko = kv[(size_t)s * (KVR + ROPE) + KVR + dro];
        kvv = xk * c + sgn * xko * sn;
    } else {
        qv = q[(size_t)s * (NH * QDIM) + h * QDIM + d];
        kvv = kvup[(size_t)s * (NH * 2 * HD) + h * (2 * HD) + (d - ROPE)];
    }
    qT[((size_t)h * QDIM + d) * S_LEN + s] = qv * SCALE_F;
    kT[((size_t)h * QDIM + d) * S_LEN + s] = kvv;
}

// ---------------- Flash attention (causal), fp32 ----------------
#define AM 64
#define AN 64
#define SP_STRIDE 68
#define ATTN_SMEM ((QDIM * AM * 2 + AN * HD + AN * SP_STRIDE) * 4)

__global__ void __launch_bounds__(256) attn_kernel(const float* __restrict__ qT,
                                                   const float* __restrict__ kT,
                                                   const float* __restrict__ kvup,
                                                   float* __restrict__ outp) {
    extern __shared__ float sh[];
    float* sQ = sh;
    float* sK = sQ + QDIM * AM;
    float* sV = sK + QDIM * AN;
    float* sP = sV + AN * HD;

    const int qb = (gridDim.x - 1 - blockIdx.x) * AM;
    const int h = blockIdx.y;
    const int tid = threadIdx.x;
    const int tx = tid & 15;
    const int ty = tid >> 4;

    const float* qbase = qT + (size_t)h * QDIM * S_LEN;
    const float* kbase = kT + (size_t)h * QDIM * S_LEN;
    const float* vbase = kvup + h * (2 * HD) + HD;

    for (int p = tid; p < QDIM * AM; p += 256) {
        const int d = p >> 6, j = p & 63;
        sQ[d * AM + j] = qbase[(size_t)d * S_LEN + qb + j];
    }

    float m_r[4], l_r[4], o_r[4][8];
#pragma unroll
    for (int a = 0; a < 4; a++) {
        m_r[a] = -1e30f;
        l_r[a] = 0.f;
#pragma unroll
        for (int c = 0; c < 8; c++) o_r[a][c] = 0.f;
    }

    const int ntiles = qb / AN + 1;
    for (int t = 0; t < ntiles; ++t) {
        const int kb = t * AN;
        __syncthreads();
        for (int p = tid; p < QDIM * AN; p += 256) {
            const int d = p >> 6, j = p & 63;
            sK[d * AN + j] = kbase[(size_t)d * S_LEN + kb + j];
        }
        for (int p = tid; p < AN * HD; p += 256) {
            const int j = p >> 7, dv = p & 127;
            sV[j * HD + dv] = vbase[(size_t)(kb + j) * (NH * 2 * HD) + dv];
        }
        __syncthreads();

        float s[4][4];
#pragma unroll
        for (int a = 0; a < 4; a++)
#pragma unroll
            for (int b = 0; b < 4; b++) s[a][b] = 0.f;

#pragma unroll 4
        for (int k = 0; k < QDIM; ++k) {
            float4 qa = *(const float4*)&sQ[k * AM + ty * 4];
            float4 kb4 = *(const float4*)&sK[k * AN + tx * 4];
            float av[4] = {qa.x, qa.y, qa.z, qa.w};
            float bv[4] = {kb4.x, kb4.y, kb4.z, kb4.w};
#pragma unroll
            for (int a = 0; a < 4; a++)
#pragma unroll
                for (int b = 0; b < 4; b++)
                    s[a][b] = fmaf(av[a], bv[b], s[a][b]);
        }

        if (t == ntiles - 1) {
#pragma unroll
            for (int a = 0; a < 4; a++)
#pragma unroll
                for (int b = 0; b < 4; b++)
                    if (tx * 4 + b > ty * 4 + a) s[a][b] = -1e30f;
        }

#pragma unroll
        for (int a = 0; a < 4; a++) {
            float mx = fmaxf(fmaxf(s[a][0], s[a][1]), fmaxf(s[a][2], s[a][3]));
#pragma unroll
            for (int o = 1; o < 16; o <<= 1) mx = fmaxf(mx, __shfl_xor_sync(0xffffffff, mx, o));
            const float mnew = fmaxf(m_r[a], mx);
            const float alpha = __expf(m_r[a] - mnew);
            float rs = 0.f;
#pragma unroll
            for (int b = 0; b < 4; b++) {
                const float pv = __expf(s[a][b] - mnew);
                s[a][b] = pv;
                rs += pv;
            }
#pragma unroll
            for (int o = 1; o < 16; o <<= 1) rs += __shfl_xor_sync(0xffffffff, rs, o);
            l_r[a] = l_r[a] * alpha + rs;
            m_r[a] = mnew;
#pragma unroll
            for (int c = 0; c < 8; c++) o_r[a][c] *= alpha;
#pragma unroll
            for (int b = 0; b < 4; b++)
                sP[(tx * 4 + b) * SP_STRIDE + ty * 4 + a] = s[a][b];
        }
        __syncthreads();

#pragma unroll 4
        for (int j = 0; j < AN; ++j) {
            float4 pv = *(const float4*)&sP[j * SP_STRIDE + ty * 4];
            float4 v0 = *(const float4*)&sV[j * HD + tx * 8];
            float4 v1 = *(const float4*)&sV[j * HD + tx * 8 + 4];
            float pa[4] = {pv.x, pv.y, pv.z, pv.w};
            float vv[8] = {v0.x, v0.y, v0.z, v0.w, v1.x, v1.y, v1.z, v1.w};
#pragma unroll
            for (int a = 0; a < 4; a++)
#pragma unroll
                for (int c = 0; c < 8; c++)
                    o_r[a][c] = fmaf(pa[a], vv[c], o_r[a][c]);
        }
    }

#pragma unroll
    for (int a = 0; a < 4; a++) {
        const float inv = 1.f / l_r[a];
        const int row = qb + ty * 4 + a;
        float* dst = outp + (size_t)row * (NH * HD) + h * HD + tx * 8;
#pragma unroll
        for (int c = 0; c < 8; c++) dst[c] = o_r[a][c] * inv;
    }
}

// ---------------- launch ----------------
static inline void split_launch(const float* in, __nv_bfloat16* hi, __nv_bfloat16* lo, int n) {
    split_kernel<<<(n / 4 + 255) / 256, 256>>>(in, hi, lo, n);
}

extern "C" void kernel_launch(void* const* d_in, const int* in_sizes, int n_in,
                              void* d_out, int out_size) {
    const float* x          = (const float*)d_in[0];
    const float* cosp       = (const float*)d_in[1];
    const float* sinp       = (const float*)d_in[2];
    const float* q_a_w      = (const float*)d_in[3];
    const float* q_a_norm_w = (const float*)d_in[4];
    const float* q_b_w      = (const float*)d_in[5];
    const float* kv_a_w     = (const float*)d_in[6];
    const float* kv_a_norm_w= (const float*)d_in[7];
    const float* kv_b_w     = (const float*)d_in[8];
    const float* o_w        = (const float*)d_in[9];

    float *qlat, *q, *kv, *kvn, *kvup, *qT, *kT, *attn;
    __nv_bfloat16 *xh, *xl, *ah, *al, *wh, *wl;
    cudaGetSymbolAddress((void**)&qlat, g_qlat);
    cudaGetSymbolAddress((void**)&q,    g_q);
    cudaGetSymbolAddress((void**)&kv,   g_kv);
    cudaGetSymbolAddress((void**)&kvn,  g_kvn);
    cudaGetSymbolAddress((void**)&kvup, g_kvup);
    cudaGetSymbolAddress((void**)&qT,   g_qT);
    cudaGetSymbolAddress((void**)&kT,   g_kT);
    cudaGetSymbolAddress((void**)&attn, g_attn);
    cudaGetSymbolAddress((void**)&xh,   g_xh);
    cudaGetSymbolAddress((void**)&xl,   g_xl);
    cudaGetSymbolAddress((void**)&ah,   g_ah);
    cudaGetSymbolAddress((void**)&al,   g_al);
    cudaGetSymbolAddress((void**)&wh,   g_wh);
    cudaGetSymbolAddress((void**)&wl,   g_wl);

    // split x once (used by GEMM 1 and 4)
    split_launch(x, xh, xl, S_LEN * HID);

    // 1) q_lat = x @ q_a_w^T   [2048,1536] K=4096
    split_launch(q_a_w, wh, wl, QR * HID);
    gemm_bf16x3<<<dim3(QR / 128, S_LEN / 128), 256>>>(xh, xl, wh, wl, qlat, S_LEN, QR, HID);
    // 2) rmsnorm(q_lat)
    rmsnorm_kernel<<<S_LEN, 256>>>(qlat, q_a_norm_w, qlat, QR, QR, QR);
    // 3) q = q_lat @ q_b_w^T   [2048,6144] K=1536
    split_launch(qlat, ah, al, S_LEN * QR);
    split_launch(q_b_w, wh, wl, NH * QDIM * QR);
    gemm_bf16x3<<<dim3((NH * QDIM) / 128, S_LEN / 128), 256>>>(ah, al, wh, wl, q, S_LEN, NH * QDIM, QR);
    // 4) kv = x @ kv_a_w^T     [2048,960] K=4096
    split_launch(kv_a_w, wh, wl, (KVR + ROPE) * HID);
    gemm_bf16x3<<<dim3((KVR + ROPE + 127) / 128, S_LEN / 128), 256>>>(xh, xl, wh, wl, kv, S_LEN, KVR + ROPE, HID);
    // 5) rmsnorm(kv[:, :896]) -> kvn
    rmsnorm_kernel<<<S_LEN, 256>>>(kv, kv_a_norm_w, kvn, KVR, KVR + ROPE, KVR);
    // 6) kv_up = kvn @ kv_b_w^T [2048,8192] K=896
    split_launch(kvn, ah, al, S_LEN * KVR);
    split_launch(kv_b_w, wh, wl, NH * 2 * HD * KVR);
    gemm_bf16x3<<<dim3((NH * 2 * HD) / 128, S_LEN / 128), 256>>>(ah, al, wh, wl, kvup, S_LEN, NH * 2 * HD, KVR);
    // 7) rope + pack
    rope_pack<<<dim3(S_LEN, NH), QDIM>>>(q, kv, kvup, cosp, sinp, qT, kT);
    // 8) causal flash attention (fp32)
    cudaFuncSetAttribute(attn_kernel, cudaFuncAttributeMaxDynamicSharedMemorySize, ATTN_SMEM);
    attn_kernel<<<dim3(S_LEN / AM, NH), 256, ATTN_SMEM>>>(qT, kT, kvup, attn);
    // 9) out = attn @ o_w^T    [2048,4096] K=4096
    split_launch(attn, ah, al, S_LEN * NH * HD);
    split_launch(o_w, wh, wl, HID * NH * HD);
    gemm_bf16x3<<<dim3(HID / 128, S_LEN / 128), 256>>>(ah, al, wh, wl, (float*)d_out, S_LEN, HID, HID);
}

// round 5
// speedup vs baseline: 2.6447x; 1.6454x over previous
#include <cuda_runtime.h>
#include <cuda_bf16.h>
#include <cstdint>

#define S_LEN 2048
#define HID   4096
#define NH    32
#define HD    128
#define ROPE  64
#define QR    1536
#define KVR   896
#define QDIM  192                 // ROPE + HD
#define EPS   1e-6f
#define SCALE_F 0.07216878364870322f  // 1/sqrt(192)

// ---------------- scratch (device globals; no allocation allowed) ----------------
__device__ float g_qlat[S_LEN * QR];
__device__ float g_q[S_LEN * NH * QDIM];
__device__ float g_kv[S_LEN * (KVR + ROPE)];
__device__ float g_kvn[S_LEN * KVR];
__device__ float g_kvup[S_LEN * NH * 2 * HD];
__device__ float g_attn[S_LEN * NH * HD];

// bf16 hi/lo split buffers (GEMM)
__device__ __nv_bfloat16 g_xh[S_LEN * HID];
__device__ __nv_bfloat16 g_xl[S_LEN * HID];
__device__ __nv_bfloat16 g_ah[S_LEN * HID];
__device__ __nv_bfloat16 g_al[S_LEN * HID];
__device__ __nv_bfloat16 g_wh[HID * HID];
__device__ __nv_bfloat16 g_wl[HID * HID];

// attention operand buffers
__device__ __nv_bfloat16 g_qbh[(size_t)NH * S_LEN * QDIM];  // [h][s][d], scaled
__device__ __nv_bfloat16 g_qbl[(size_t)NH * S_LEN * QDIM];
__device__ __nv_bfloat16 g_kbh[(size_t)NH * S_LEN * QDIM];
__device__ __nv_bfloat16 g_kbl[(size_t)NH * S_LEN * QDIM];
__device__ __nv_bfloat16 g_vbh[(size_t)NH * HD * S_LEN];    // [h][dv][s]
__device__ __nv_bfloat16 g_vbl[(size_t)NH * HD * S_LEN];

// ---------------- fp32 -> (bf16 hi, bf16 lo) split ----------------
__global__ void split_kernel(const float* __restrict__ in, __nv_bfloat16* __restrict__ hi,
                             __nv_bfloat16* __restrict__ lo, int n) {
    int i = (blockIdx.x * blockDim.x + threadIdx.x) * 4;
    if (i >= n) return;
    float4 v = *(const float4*)(in + i);
    float vv[4] = {v.x, v.y, v.z, v.w};
    __nv_bfloat16 h[4], l[4];
#pragma unroll
    for (int j = 0; j < 4; j++) {
        h[j] = __float2bfloat16(vv[j]);
        l[j] = __float2bfloat16(vv[j] - __bfloat162float(h[j]));
    }
    __nv_bfloat162* hp = (__nv_bfloat162*)(hi + i);
    __nv_bfloat162* lp = (__nv_bfloat162*)(lo + i);
    hp[0] = __halves2bfloat162(h[0], h[1]);
    hp[1] = __halves2bfloat162(h[2], h[3]);
    lp[0] = __halves2bfloat162(l[0], l[1]);
    lp[1] = __halves2bfloat162(l[2], l[3]);
}

// ---------------- split-bf16 tensor-core GEMM (validated in R3) ----------------
#define BM 128
#define BN 128
#define BK 32
#define LDSB 40

#define MMA_BF16(c, a, b)                                                            \
    asm volatile(                                                                    \
        "mma.sync.aligned.m16n8k16.row.col.f32.bf16.bf16.f32 "                       \
        "{%0,%1,%2,%3}, {%4,%5,%6,%7}, {%8,%9}, {%0,%1,%2,%3};"                      \
        : "+f"(c[0]), "+f"(c[1]), "+f"(c[2]), "+f"(c[3])                             \
        : "r"(a[0]), "r"(a[1]), "r"(a[2]), "r"(a[3]), "r"(b[0]), "r"(b[1]))

#define LDMX4(r, p)                                                                  \
    asm volatile("ldmatrix.sync.aligned.m8n8.x4.shared.b16 {%0,%1,%2,%3}, [%4];"     \
                 : "=r"(r[0]), "=r"(r[1]), "=r"(r[2]), "=r"(r[3])                    \
                 : "r"((uint32_t)__cvta_generic_to_shared(p)))

__global__ void __launch_bounds__(256) gemm_bf16x3(
    const __nv_bfloat16* __restrict__ Ah, const __nv_bfloat16* __restrict__ Al,
    const __nv_bfloat16* __restrict__ Bh, const __nv_bfloat16* __restrict__ Bl,
    float* __restrict__ C, int M, int N, int K) {
    __shared__ __nv_bfloat16 sAh[BM * LDSB];
    __shared__ __nv_bfloat16 sAl[BM * LDSB];
    __shared__ __nv_bfloat16 sBh[BN * LDSB];
    __shared__ __nv_bfloat16 sBl[BN * LDSB];

    const int bm = blockIdx.y * BM;
    const int bn = blockIdx.x * BN;
    const int tid = threadIdx.x;
    const int wid = tid >> 5, lane = tid & 31;
    const int wm = (wid >> 2) * 64;
    const int wn = (wid & 3) * 32;

    const int lr = tid >> 1;
    const int lk = (tid & 1) * 16;
    const __nv_bfloat16* gAh = Ah + (size_t)(bm + lr) * K + lk;
    const __nv_bfloat16* gAl = Al + (size_t)(bm + lr) * K + lk;
    const int brow = min(bn + lr, N - 1);
    const __nv_bfloat16* gBh = Bh + (size_t)brow * K + lk;
    const __nv_bfloat16* gBl = Bl + (size_t)brow * K + lk;

    float acc[4][4][4];
#pragma unroll
    for (int i = 0; i < 4; i++)
#pragma unroll
        for (int j = 0; j < 4; j++)
#pragma unroll
            for (int r = 0; r < 4; r++) acc[i][j][r] = 0.f;

    uint4 pah0 = *(const uint4*)(gAh),     pah1 = *(const uint4*)(gAh + 8);
    uint4 pal0 = *(const uint4*)(gAl),     pal1 = *(const uint4*)(gAl + 8);
    uint4 pbh0 = *(const uint4*)(gBh),     pbh1 = *(const uint4*)(gBh + 8);
    uint4 pbl0 = *(const uint4*)(gBl),     pbl1 = *(const uint4*)(gBl + 8);

    for (int k0 = 0; k0 < K; k0 += BK) {
        __syncthreads();
        *(uint4*)&sAh[lr * LDSB + lk] = pah0;  *(uint4*)&sAh[lr * LDSB + lk + 8] = pah1;
        *(uint4*)&sAl[lr * LDSB + lk] = pal0;  *(uint4*)&sAl[lr * LDSB + lk + 8] = pal1;
        *(uint4*)&sBh[lr * LDSB + lk] = pbh0;  *(uint4*)&sBh[lr * LDSB + lk + 8] = pbh1;
        *(uint4*)&sBl[lr * LDSB + lk] = pbl0;  *(uint4*)&sBl[lr * LDSB + lk + 8] = pbl1;
        __syncthreads();

        if (k0 + BK < K) {
            pah0 = *(const uint4*)(gAh + k0 + BK);  pah1 = *(const uint4*)(gAh + k0 + BK + 8);
            pal0 = *(const uint4*)(gAl + k0 + BK);  pal1 = *(const uint4*)(gAl + k0 + BK + 8);
            pbh0 = *(const uint4*)(gBh + k0 + BK);  pbh1 = *(const uint4*)(gBh + k0 + BK + 8);
            pbl0 = *(const uint4*)(gBl + k0 + BK);  pbl1 = *(const uint4*)(gBl + k0 + BK + 8);
        }

#pragma unroll
        for (int kk = 0; kk < BK; kk += 16) {
            uint32_t a_h[4][4], a_l[4][4], b_h[4][2], b_l[4][2];
            const int ar = wm + (lane & 15);
            const int ac = kk + (lane >> 4) * 8;
#pragma unroll
            for (int mi = 0; mi < 4; mi++) {
                LDMX4(a_h[mi], &sAh[(ar + mi * 16) * LDSB + ac]);
                LDMX4(a_l[mi], &sAl[(ar + mi * 16) * LDSB + ac]);
            }
            const int br = wn + (lane & 7);
            const int bc = kk + ((lane >> 3) & 1) * 8;
#pragma unroll
            for (int nj = 0; nj < 4; nj++) {
                asm volatile("ldmatrix.sync.aligned.m8n8.x2.shared.b16 {%0,%1}, [%2];"
                             : "=r"(b_h[nj][0]), "=r"(b_h[nj][1])
                             : "r"((uint32_t)__cvta_generic_to_shared(&sBh[(br + nj * 8) * LDSB + bc])));
                asm volatile("ldmatrix.sync.aligned.m8n8.x2.shared.b16 {%0,%1}, [%2];"
                             : "=r"(b_l[nj][0]), "=r"(b_l[nj][1])
                             : "r"((uint32_t)__cvta_generic_to_shared(&sBl[(br + nj * 8) * LDSB + bc])));
            }
#pragma unroll
            for (int mi = 0; mi < 4; mi++)
#pragma unroll
                for (int nj = 0; nj < 4; nj++) {
                    MMA_BF16(acc[mi][nj], a_h[mi], b_h[nj]);
                    MMA_BF16(acc[mi][nj], a_h[mi], b_l[nj]);
                    MMA_BF16(acc[mi][nj], a_l[mi], b_h[nj]);
                }
        }
    }

#pragma unroll
    for (int mi = 0; mi < 4; mi++) {
#pragma unroll
        for (int nj = 0; nj < 4; nj++) {
            const int row0 = bm + wm + mi * 16 + (lane >> 2);
            const int col = bn + wn + nj * 8 + (lane & 3) * 2;
            if (col < N) {
                C[(size_t)row0 * N + col]       = acc[mi][nj][0];
                C[(size_t)row0 * N + col + 1]   = acc[mi][nj][1];
                C[(size_t)(row0 + 8) * N + col]     = acc[mi][nj][2];
                C[(size_t)(row0 + 8) * N + col + 1] = acc[mi][nj][3];
            }
        }
    }
}

// ---------------- RMSNorm ----------------
__global__ void rmsnorm_kernel(const float* __restrict__ in, const float* __restrict__ w,
                               float* __restrict__ out, int n, int in_stride, int out_stride) {
    const int row = blockIdx.x;
    const float* p = in + (size_t)row * in_stride;
    float ss = 0.f;
    for (int i = threadIdx.x; i < n; i += blockDim.x) {
        float v = p[i];
        ss += v * v;
    }
    __shared__ float red[8];
#pragma unroll
    for (int o = 16; o > 0; o >>= 1) ss += __shfl_xor_sync(0xffffffff, ss, o);
    if ((threadIdx.x & 31) == 0) red[threadIdx.x >> 5] = ss;
    __syncthreads();
    if (threadIdx.x < 8) {
        float v = red[threadIdx.x];
#pragma unroll
        for (int o = 4; o > 0; o >>= 1) v += __shfl_xor_sync(0xff, v, o);
        if (threadIdx.x == 0) red[0] = v;
    }
    __syncthreads();
    const float scale = rsqrtf(red[0] / (float)n + EPS);
    float* q = out + (size_t)row * out_stride;
    for (int i = threadIdx.x; i < n; i += blockDim.x) q[i] = p[i] * scale * w[i];
}

// ---------------- RoPE + pack Q/K as bf16 hi/lo [h][s][d] ----------------
__global__ void rope_pack_bf16(const float* __restrict__ q, const float* __restrict__ kv,
                               const float* __restrict__ kvup,
                               const float* __restrict__ cosT, const float* __restrict__ sinT,
                               __nv_bfloat16* __restrict__ qh, __nv_bfloat16* __restrict__ ql,
                               __nv_bfloat16* __restrict__ kh, __nv_bfloat16* __restrict__ kl) {
    const int s = blockIdx.x;
    const int h = blockIdx.y;
    const int d = threadIdx.x;  // 0..191

    float qv, kvv;
    if (d < ROPE) {
        const float c = cosT[s * ROPE + d];
        const float sn = sinT[s * ROPE + d];
        const int dro = (d < 32) ? d + 32 : d - 32;
        const float sgn = (d < 32) ? -1.f : 1.f;
        const float xq = q[(size_t)s * (NH * QDIM) + h * QDIM + d];
        const float xqo = q[(size_t)s * (NH * QDIM) + h * QDIM + dro];
        qv = xq * c + sgn * xqo * sn;
        const float xk = kv[(size_t)s * (KVR + ROPE) + KVR + d];
        const float xko = kv[(size_t)s * (KVR + ROPE) + KVR + dro];
        kvv = xk * c + sgn * xko * sn;
    } else {
        qv = q[(size_t)s * (NH * QDIM) + h * QDIM + d];
        kvv = kvup[(size_t)s * (NH * 2 * HD) + h * (2 * HD) + (d - ROPE)];
    }
    qv *= SCALE_F;
    const size_t o = ((size_t)h * S_LEN + s) * QDIM + d;
    __nv_bfloat16 hq = __float2bfloat16(qv);
    qh[o] = hq;
    ql[o] = __float2bfloat16(qv - __bfloat162float(hq));
    __nv_bfloat16 hk = __float2bfloat16(kvv);
    kh[o] = hk;
    kl[o] = __float2bfloat16(kvv - __bfloat162float(hk));
}

// ---------------- V transpose-pack: kvup[s][h][128+dv] -> [h][dv][s] bf16 hi/lo ----------------
__global__ void v_pack(const float* __restrict__ kvup,
                       __nv_bfloat16* __restrict__ vh, __nv_bfloat16* __restrict__ vl) {
    __shared__ float tile[32][33];
    const int s0 = blockIdx.x * 32, d0 = blockIdx.y * 32, h = blockIdx.z;
    const int tx = threadIdx.x, ty = threadIdx.y;
#pragma unroll
    for (int i = 0; i < 4; i++) {
        const int s = s0 + ty + i * 8;
        tile[ty + i * 8][tx] = kvup[(size_t)s * (NH * 2 * HD) + h * (2 * HD) + HD + d0 + tx];
    }
    __syncthreads();
#pragma unroll
    for (int i = 0; i < 4; i++) {
        const int dv = d0 + ty + i * 8;
        const float v = tile[tx][ty + i * 8];
        __nv_bfloat16 hv = __float2bfloat16(v);
        const size_t o = ((size_t)(h * HD + dv)) * S_LEN + s0 + tx;
        vh[o] = hv;
        vl[o] = __float2bfloat16(v - __bfloat162float(hv));
    }
}

// ---------------- tensor-core flash attention (causal) ----------------
// 256 threads = 8 warps, q-tile 128 (warp = m16), k-tile 64.
#define QSTR 200   // bf16 stride for 192-wide rows
#define VSTR 72    // bf16 stride for 64-wide rows
#define ATTN_SMEM ((128 * QSTR * 2 + 64 * QSTR * 2 + 128 * VSTR * 2) * 2)

__device__ __forceinline__ uint32_t pack_bf2(float a, float b) {
    __nv_bfloat162 t = __floats2bfloat162_rn(a, b);  // lo=a, hi=b
    return *(uint32_t*)&t;
}

__global__ void __launch_bounds__(256) attn_mma(
    const __nv_bfloat16* __restrict__ qh, const __nv_bfloat16* __restrict__ ql,
    const __nv_bfloat16* __restrict__ kh, const __nv_bfloat16* __restrict__ kl,
    const __nv_bfloat16* __restrict__ vh, const __nv_bfloat16* __restrict__ vl,
    float* __restrict__ outp) {
    extern __shared__ __nv_bfloat16 sm[];
    __nv_bfloat16* sQh = sm;
    __nv_bfloat16* sQl = sQh + 128 * QSTR;
    __nv_bfloat16* sKh = sQl + 128 * QSTR;
    __nv_bfloat16* sKl = sKh + 64 * QSTR;
    __nv_bfloat16* sVh = sKl + 64 * QSTR;
    __nv_bfloat16* sVl = sVh + 128 * VSTR;

    const int qb = (gridDim.x - 1 - blockIdx.x) * 128;  // heavy blocks first
    const int h = blockIdx.y;
    const int tid = threadIdx.x;
    const int wid = tid >> 5, lane = tid & 31;

    // load Q tile (persistent)
    const __nv_bfloat16* qhb = qh + ((size_t)h * S_LEN + qb) * QDIM;
    const __nv_bfloat16* qlb = ql + ((size_t)h * S_LEN + qb) * QDIM;
    for (int i = tid; i < 128 * 24; i += 256) {
        const int r = i / 24, c = (i % 24) * 8;
        *(uint4*)&sQh[r * QSTR + c] = *(const uint4*)&qhb[(size_t)r * QDIM + c];
        *(uint4*)&sQl[r * QSTR + c] = *(const uint4*)&qlb[(size_t)r * QDIM + c];
    }

    float o_r[16][4];
#pragma unroll
    for (int n = 0; n < 16; n++)
#pragma unroll
        for (int r = 0; r < 4; r++) o_r[n][r] = 0.f;
    float m0 = -1e30f, m1 = -1e30f, l0 = 0.f, l1 = 0.f;

    const int r0w = qb + wid * 16 + (lane >> 2);
    const int r1w = r0w + 8;

    const __nv_bfloat16* khb = kh + (size_t)h * S_LEN * QDIM;
    const __nv_bfloat16* klb = kl + (size_t)h * S_LEN * QDIM;
    const __nv_bfloat16* vhb = vh + (size_t)h * HD * S_LEN;
    const __nv_bfloat16* vlb = vl + (size_t)h * HD * S_LEN;

    const int ntiles = qb / 64 + 2;
    for (int t = 0; t < ntiles; t++) {
        const int kb = t * 64;
        __syncthreads();
        for (int i = tid; i < 64 * 24; i += 256) {
            const int r = i / 24, c = (i % 24) * 8;
            *(uint4*)&sKh[r * QSTR + c] = *(const uint4*)&khb[(size_t)(kb + r) * QDIM + c];
            *(uint4*)&sKl[r * QSTR + c] = *(const uint4*)&klb[(size_t)(kb + r) * QDIM + c];
        }
        for (int i = tid; i < 128 * 8; i += 256) {
            const int r = i / 8, c = (i % 8) * 8;
            *(uint4*)&sVh[r * VSTR + c] = *(const uint4*)&vhb[(size_t)r * S_LEN + kb + c];
            *(uint4*)&sVl[r * VSTR + c] = *(const uint4*)&vlb[(size_t)r * S_LEN + kb + c];
        }
        __syncthreads();

        if (kb > qb + wid * 16 + 15) continue;  // fully masked for this warp

        // ---- scores = Q K^T (3-MMA split) ----
        float sc[8][4];
#pragma unroll
        for (int j = 0; j < 8; j++)
#pragma unroll
            for (int r = 0; r < 4; r++) sc[j][r] = 0.f;

        const int arow = wid * 16 + (lane & 15);
        const int xcol = (lane >> 4) * 8;
#pragma unroll
        for (int ks = 0; ks < 12; ks++) {
            uint32_t aH[4], aL[4];
            LDMX4(aH, &sQh[arow * QSTR + ks * 16 + xcol]);
            LDMX4(aL, &sQl[arow * QSTR + ks * 16 + xcol]);
#pragma unroll
            for (int g = 0; g < 4; g++) {
                uint32_t rh[4], rl[4];
                LDMX4(rh, &sKh[(g * 16 + (lane & 15)) * QSTR + ks * 16 + xcol]);
                LDMX4(rl, &sKl[(g * 16 + (lane & 15)) * QSTR + ks * 16 + xcol]);
                uint32_t bh0[2] = {rh[0], rh[2]}, bh1[2] = {rh[1], rh[3]};
                uint32_t bl0[2] = {rl[0], rl[2]}, bl1[2] = {rl[1], rl[3]};
                MMA_BF16(sc[2 * g],     aH, bh0);
                MMA_BF16(sc[2 * g],     aH, bl0);
                MMA_BF16(sc[2 * g],     aL, bh0);
                MMA_BF16(sc[2 * g + 1], aH, bh1);
                MMA_BF16(sc[2 * g + 1], aH, bl1);
                MMA_BF16(sc[2 * g + 1], aL, bh1);
            }
        }

        // ---- causal mask ----
        if (kb + 63 > r0w) {
#pragma unroll
            for (int j = 0; j < 8; j++) {
                const int colg = kb + j * 8 + (lane & 3) * 2;
                if (colg     > r0w) sc[j][0] = -1e30f;
                if (colg + 1 > r0w) sc[j][1] = -1e30f;
                if (colg     > r1w) sc[j][2] = -1e30f;
                if (colg + 1 > r1w) sc[j][3] = -1e30f;
            }
        }

        // ---- online softmax (rows owned by 4-lane groups) ----
        float mx0 = -1e30f, mx1 = -1e30f;
#pragma unroll
        for (int j = 0; j < 8; j++) {
            mx0 = fmaxf(mx0, fmaxf(sc[j][0], sc[j][1]));
            mx1 = fmaxf(mx1, fmaxf(sc[j][2], sc[j][3]));
        }
        mx0 = fmaxf(mx0, __shfl_xor_sync(0xffffffff, mx0, 1));
        mx0 = fmaxf(mx0, __shfl_xor_sync(0xffffffff, mx0, 2));
        mx1 = fmaxf(mx1, __shfl_xor_sync(0xffffffff, mx1, 1));
        mx1 = fmaxf(mx1, __shfl_xor_sync(0xffffffff, mx1, 2));
        const float mn0 = fmaxf(m0, mx0), mn1 = fmaxf(m1, mx1);
        const float al0 = __expf(m0 - mn0), al1 = __expf(m1 - mn1);
        float rs0 = 0.f, rs1 = 0.f;
#pragma unroll
        for (int j = 0; j < 8; j++) {
            sc[j][0] = __expf(sc[j][0] - mn0);
            sc[j][1] = __expf(sc[j][1] - mn0);
            sc[j][2] = __expf(sc[j][2] - mn1);
            sc[j][3] = __expf(sc[j][3] - mn1);
            rs0 += sc[j][0] + sc[j][1];
            rs1 += sc[j][2] + sc[j][3];
        }
        rs0 += __shfl_xor_sync(0xffffffff, rs0, 1);
        rs0 += __shfl_xor_sync(0xffffffff, rs0, 2);
        rs1 += __shfl_xor_sync(0xffffffff, rs1, 1);
        rs1 += __shfl_xor_sync(0xffffffff, rs1, 2);
        l0 = l0 * al0 + rs0;
        l1 = l1 * al1 + rs1;
        m0 = mn0;
        m1 = mn1;
#pragma unroll
        for (int n = 0; n < 16; n++) {
            o_r[n][0] *= al0; o_r[n][1] *= al0;
            o_r[n][2] *= al1; o_r[n][3] *= al1;
        }

        // ---- O += P V  (P split hi/lo: PhVh + PhVl + PlVh) ----
#pragma unroll
        for (int ku = 0; ku < 4; ku++) {
            // hi/lo split of the 8 P values feeding this k-slice
            float ph[8], pl[8];
#pragma unroll
            for (int e = 0; e < 4; e++) {
                const float v0 = sc[2 * ku][e], v1 = sc[2 * ku + 1][e];
                const float h0 = __bfloat162float(__float2bfloat16(v0));
                const float h1 = __bfloat162float(__float2bfloat16(v1));
                ph[e] = h0;     pl[e] = v0 - h0;
                ph[4 + e] = h1; pl[4 + e] = v1 - h1;
            }
            uint32_t aPh[4], aPl[4];
            aPh[0] = pack_bf2(ph[0], ph[1]);  aPl[0] = pack_bf2(pl[0], pl[1]);
            aPh[1] = pack_bf2(ph[2], ph[3]);  aPl[1] = pack_bf2(pl[2], pl[3]);
            aPh[2] = pack_bf2(ph[4], ph[5]);  aPl[2] = pack_bf2(pl[4], pl[5]);
            aPh[3] = pack_bf2(ph[6], ph[7]);  aPl[3] = pack_bf2(pl[6], pl[7]);
            const int vc = ku * 16 + xcol;
#pragma unroll
            for (int g = 0; g < 8; g++) {
                uint32_t rh[4], rl[4];
                LDMX4(rh, &sVh[(g * 16 + (lane & 15)) * VSTR + vc]);
                LDMX4(rl, &sVl[(g * 16 + (lane & 15)) * VSTR + vc]);
                uint32_t bh0[2] = {rh[0], rh[2]}, bh1[2] = {rh[1], rh[3]};
                uint32_t bl0[2] = {rl[0], rl[2]}, bl1[2] = {rl[1], rl[3]};
                MMA_BF16(o_r[2 * g],     aPh, bh0);
                MMA_BF16(o_r[2 * g],     aPh, bl0);
                MMA_BF16(o_r[2 * g],     aPl, bh0);
                MMA_BF16(o_r[2 * g + 1], aPh, bh1);
                MMA_BF16(o_r[2 * g + 1], aPh, bl1);
                MMA_BF16(o_r[2 * g + 1], aPl, bh1);
            }
        }
    }

    // ---- normalize + store ----
    const float inv0 = 1.f / l0, inv1 = 1.f / l1;
#pragma unroll
    for (int n = 0; n < 16; n++) {
        const int col = h * HD + n * 8 + (lane & 3) * 2;
        outp[(size_t)r0w * (NH * HD) + col]     = o_r[n][0] * inv0;
        outp[(size_t)r0w * (NH * HD) + col + 1] = o_r[n][1] * inv0;
        outp[(size_t)r1w * (NH * HD) + col]     = o_r[n][2] * inv1;
        outp[(size_t)r1w * (NH * HD) + col + 1] = o_r[n][3] * inv1;
    }
}

// ---------------- launch ----------------
static inline void split_launch(const float* in, __nv_bfloat16* hi, __nv_bfloat16* lo, int n) {
    split_kernel<<<(n / 4 + 255) / 256, 256>>>(in, hi, lo, n);
}

extern "C" void kernel_launch(void* const* d_in, const int* in_sizes, int n_in,
                              void* d_out, int out_size) {
    const float* x          = (const float*)d_in[0];
    const float* cosp       = (const float*)d_in[1];
    const float* sinp       = (const float*)d_in[2];
    const float* q_a_w      = (const float*)d_in[3];
    const float* q_a_norm_w = (const float*)d_in[4];
    const float* q_b_w      = (const float*)d_in[5];
    const float* kv_a_w     = (const float*)d_in[6];
    const float* kv_a_norm_w= (const float*)d_in[7];
    const float* kv_b_w     = (const float*)d_in[8];
    const float* o_w        = (const float*)d_in[9];

    float *qlat, *q, *kv, *kvn, *kvup, *attn;
    __nv_bfloat16 *xh, *xl, *ah, *al, *wh, *wl;
    __nv_bfloat16 *qbh, *qbl, *kbh, *kbl, *vbh, *vbl;
    cudaGetSymbolAddress((void**)&qlat, g_qlat);
    cudaGetSymbolAddress((void**)&q,    g_q);
    cudaGetSymbolAddress((void**)&kv,   g_kv);
    cudaGetSymbolAddress((void**)&kvn,  g_kvn);
    cudaGetSymbolAddress((void**)&kvup, g_kvup);
    cudaGetSymbolAddress((void**)&attn, g_attn);
    cudaGetSymbolAddress((void**)&xh,   g_xh);
    cudaGetSymbolAddress((void**)&xl,   g_xl);
    cudaGetSymbolAddress((void**)&ah,   g_ah);
    cudaGetSymbolAddress((void**)&al,   g_al);
    cudaGetSymbolAddress((void**)&wh,   g_wh);
    cudaGetSymbolAddress((void**)&wl,   g_wl);
    cudaGetSymbolAddress((void**)&qbh,  g_qbh);
    cudaGetSymbolAddress((void**)&qbl,  g_qbl);
    cudaGetSymbolAddress((void**)&kbh,  g_kbh);
    cudaGetSymbolAddress((void**)&kbl,  g_kbl);
    cudaGetSymbolAddress((void**)&vbh,  g_vbh);
    cudaGetSymbolAddress((void**)&vbl,  g_vbl);

    split_launch(x, xh, xl, S_LEN * HID);

    // 1) q_lat = x @ q_a_w^T
    split_launch(q_a_w, wh, wl, QR * HID);
    gemm_bf16x3<<<dim3(QR / 128, S_LEN / 128), 256>>>(xh, xl, wh, wl, qlat, S_LEN, QR, HID);
    // 2) rmsnorm
    rmsnorm_kernel<<<S_LEN, 256>>>(qlat, q_a_norm_w, qlat, QR, QR, QR);
    // 3) q = q_lat @ q_b_w^T
    split_launch(qlat, ah, al, S_LEN * QR);
    split_launch(q_b_w, wh, wl, NH * QDIM * QR);
    gemm_bf16x3<<<dim3((NH * QDIM) / 128, S_LEN / 128), 256>>>(ah, al, wh, wl, q, S_LEN, NH * QDIM, QR);
    // 4) kv = x @ kv_a_w^T
    split_launch(kv_a_w, wh, wl, (KVR + ROPE) * HID);
    gemm_bf16x3<<<dim3((KVR + ROPE + 127) / 128, S_LEN / 128), 256>>>(xh, xl, wh, wl, kv, S_LEN, KVR + ROPE, HID);
    // 5) rmsnorm
    rmsnorm_kernel<<<S_LEN, 256>>>(kv, kv_a_norm_w, kvn, KVR, KVR + ROPE, KVR);
    // 6) kv_up = kvn @ kv_b_w^T
    split_launch(kvn, ah, al, S_LEN * KVR);
    split_launch(kv_b_w, wh, wl, NH * 2 * HD * KVR);
    gemm_bf16x3<<<dim3((NH * 2 * HD) / 128, S_LEN / 128), 256>>>(ah, al, wh, wl, kvup, S_LEN, NH * 2 * HD, KVR);
    // 7) rope + pack bf16 operands
    rope_pack_bf16<<<dim3(S_LEN, NH), QDIM>>>(q, kv, kvup, cosp, sinp, qbh, qbl, kbh, kbl);
    v_pack<<<dim3(S_LEN / 32, HD / 32, NH), dim3(32, 8)>>>(kvup, vbh, vbl);
    // 8) tensor-core causal flash attention
    cudaFuncSetAttribute(attn_mma, cudaFuncAttributeMaxDynamicSharedMemorySize, ATTN_SMEM);
    attn_mma<<<dim3(S_LEN / 128, NH), 256, ATTN_SMEM>>>(qbh, qbl, kbh, kbl, vbh, vbl, attn);
    // 9) out = attn @ o_w^T
    split_launch(attn, ah, al, S_LEN * NH * HD);
    split_launch(o_w, wh, wl, HID * NH * HD);
    gemm_bf16x3<<<dim3(HID / 128, S_LEN / 128), 256>>>(ah, al, wh, wl, (float*)d_out, S_LEN, HID, HID);
}